// round 16
// baseline (speedup 1.0000x reference)
#include <cuda_runtime.h>
#include <cuda_fp16.h>
#include <math.h>
#include <stdint.h>

#define S 2048
#define D 1024
#define H 8
#define HD 8192

typedef __half half_t;
typedef long long ll;

// ------------------------- scratch (device globals) -------------------------
__device__ __align__(256) half_t g_xH[S * D], g_xL[S * D];
__device__ __align__(256) half_t g_xTH[D * S], g_xTL[D * S];
__device__ __align__(256) half_t g_hidH[S * D], g_hidL[S * D];
__device__ __align__(256) half_t g_relH[S * D], g_relL[S * D];
__device__ __align__(256) half_t g_w2TH[D * D], g_w2TL[D * D];
__device__ __align__(256) half_t g_awTH[H * D * D], g_awTL[H * D * D];
__device__ __align__(256) half_t g_owTH[D * HD], g_owTL[D * HD];
__device__ __align__(256) half_t g_scH[S * HD], g_scL[S * HD];   // [H,S,D] raw
__device__ __align__(256) float  g_attnF[(size_t)H * S * S];
__device__ __align__(256) half_t g_atH[(size_t)H * S * S];       // hi only
__device__ __align__(256) half_t g_ctxH[S * HD];                 // hi only

// ------------------------- helpers ------------------------------------------
__device__ __forceinline__ uint32_t smem_u32(const void* p) {
    uint32_t a;
    asm("{ .reg .u64 t; cvta.to.shared.u64 t, %1; cvt.u32.u64 %0, t; }"
        : "=r"(a) : "l"(p));
    return a;
}
__device__ __forceinline__ void split2h(float v, half_t& h, half_t& l) {
    h = __float2half_rn(v);
    l = __float2half_rn(v - __half2float(h));
}
__device__ __forceinline__ void ldm_x4(uint32_t* r, uint32_t addr) {
    asm volatile("ldmatrix.sync.aligned.m8n8.x4.shared.b16 {%0,%1,%2,%3}, [%4];"
                 : "=r"(r[0]), "=r"(r[1]), "=r"(r[2]), "=r"(r[3]) : "r"(addr));
}
// fp32-accum HMMA
__device__ __forceinline__ void mma16816(float* c, const uint32_t* a, const uint32_t* b) {
    asm volatile(
        "mma.sync.aligned.m16n8k16.row.col.f32.f16.f16.f32 "
        "{%0,%1,%2,%3}, {%4,%5,%6,%7}, {%8,%9}, {%0,%1,%2,%3};"
        : "+f"(c[0]), "+f"(c[1]), "+f"(c[2]), "+f"(c[3])
        : "r"(a[0]), "r"(a[1]), "r"(a[2]), "r"(a[3]), "r"(b[0]), "r"(b[1]));
}
// fp16-accum HMMA (corrections)
__device__ __forceinline__ void mma16816h(uint32_t* c, const uint32_t* a, const uint32_t* b) {
    asm volatile(
        "mma.sync.aligned.m16n8k16.row.col.f16.f16.f16.f16 "
        "{%0,%1}, {%2,%3,%4,%5}, {%6,%7}, {%0,%1};"
        : "+r"(c[0]), "+r"(c[1])
        : "r"(a[0]), "r"(a[1]), "r"(a[2]), "r"(a[3]), "r"(b[0]), "r"(b[1]));
}
#define CP_ASYNC_CG(sa, g) \
    asm volatile("cp.async.cg.shared.global [%0], [%1], 16;" :: "r"(sa), "l"(g) : "memory")
#define CP_COMMIT()  asm volatile("cp.async.commit_group;" ::: "memory")
#define CP_WAIT0()   asm volatile("cp.async.wait_group 0;" ::: "memory")

// SMEM tile geometry: 128 rows x 32 halves, padded row = 80 bytes
#define ROWB 80
#define TILEB (128 * ROWB)       // 10240
#define BUFB (4 * TILEB)         // 40960 per stage
#define SMEM_TOTAL (2 * BUFB)    // 81920

// ------------------------- conversion kernels -------------------------------
__global__ void split_x_kernel(const float* __restrict__ x) {
    int i = blockIdx.x * 256 + threadIdx.x;
    split2h(x[i], g_xH[i], g_xL[i]);
}

__global__ void relenc1_kernel(const float* __restrict__ relations,
                               const float* __restrict__ w1,
                               const float* __restrict__ b1) {
    int idx = blockIdx.x * 256 + threadIdx.x;
    int s = idx >> 10, d = idx & 1023;
    float v = b1[d];
    v = fmaf(relations[s * 4 + 0], w1[0 * D + d], v);
    v = fmaf(relations[s * 4 + 1], w1[1 * D + d], v);
    v = fmaf(relations[s * 4 + 2], w1[2 * D + d], v);
    v = fmaf(relations[s * 4 + 3], w1[3 * D + d], v);
    v = fmaxf(v, 0.0f);
    split2h(v, g_hidH[idx], g_hidL[idx]);
}

__global__ void transpose_split(const float* __restrict__ in, ll sIn,
                                int R, int C,
                                half_t* __restrict__ oH, half_t* __restrict__ oL,
                                ll sOut) {
    __shared__ float t[32][33];
    in += (ll)blockIdx.z * sIn;
    oH += (ll)blockIdx.z * sOut;
    oL += (ll)blockIdx.z * sOut;
    int r0 = blockIdx.y * 32, c0 = blockIdx.x * 32;
    int tx = threadIdx.x, ty = threadIdx.y;  // 32 x 8
#pragma unroll
    for (int i = 0; i < 4; i++)
        t[ty + i * 8][tx] = in[(ll)(r0 + ty + i * 8) * C + c0 + tx];
    __syncthreads();
#pragma unroll
    for (int i = 0; i < 4; i++) {
        float v = t[tx][ty + i * 8];
        ll o = (ll)(c0 + ty + i * 8) * R + r0 + tx;
        half_t h, l;
        split2h(v, h, l);
        oH[o] = h;
        oL[o] = l;
    }
}

// ------------------------- softmax ------------------------------------------
__global__ void softmax_kernel() {
    const ll row = blockIdx.x;  // H*S rows
    const float4* p = (const float4*)(g_attnF + row * (ll)S);
    const int tid = threadIdx.x;  // 256
    float4 a = p[tid];
    float4 b = p[tid + 256];
    __shared__ float red[8];

    float m = fmaxf(fmaxf(fmaxf(a.x, a.y), fmaxf(a.z, a.w)),
                    fmaxf(fmaxf(b.x, b.y), fmaxf(b.z, b.w)));
#pragma unroll
    for (int o = 16; o > 0; o >>= 1) m = fmaxf(m, __shfl_xor_sync(~0u, m, o));
    if ((tid & 31) == 0) red[tid >> 5] = m;
    __syncthreads();
    if (tid < 32) {
        float t = (tid < 8) ? red[tid] : -INFINITY;
#pragma unroll
        for (int o = 4; o > 0; o >>= 1) t = fmaxf(t, __shfl_xor_sync(~0u, t, o));
        if (tid == 0) red[0] = t;
    }
    __syncthreads();
    m = red[0];
    __syncthreads();

    a.x = expf(a.x - m); a.y = expf(a.y - m); a.z = expf(a.z - m); a.w = expf(a.w - m);
    b.x = expf(b.x - m); b.y = expf(b.y - m); b.z = expf(b.z - m); b.w = expf(b.w - m);
    float s = a.x + a.y + a.z + a.w + b.x + b.y + b.z + b.w;
#pragma unroll
    for (int o = 16; o > 0; o >>= 1) s += __shfl_xor_sync(~0u, s, o);
    if ((tid & 31) == 0) red[tid >> 5] = s;
    __syncthreads();
    if (tid < 32) {
        float t = (tid < 8) ? red[tid] : 0.0f;
#pragma unroll
        for (int o = 4; o > 0; o >>= 1) t += __shfl_xor_sync(~0u, t, o);
        if (tid == 0) red[0] = t;
    }
    __syncthreads();
    float inv = 1.0f / red[0];

    half_t h[8];
    h[0] = __float2half_rn(a.x * inv); h[1] = __float2half_rn(a.y * inv);
    h[2] = __float2half_rn(a.z * inv); h[3] = __float2half_rn(a.w * inv);
    h[4] = __float2half_rn(b.x * inv); h[5] = __float2half_rn(b.y * inv);
    h[6] = __float2half_rn(b.z * inv); h[7] = __float2half_rn(b.w * inv);
    ll b0 = row * (ll)S + tid * 4;
    *(uint2*)(g_atH + b0) = *(uint2*)&h[0];
    *(uint2*)(g_atH + b0 + 1024) = *(uint2*)&h[4];
}

// ------------------------- split-fp16 NT HGEMM (mma.sync) --------------------
// 128-thread CTA, 4 warps of 64x64; CTA tile 128x128, BK=32, 2-stage ring.
// Main term Ah*Bh -> fp32 accum HMMA.  Correction terms (Ah*Bl [+ Al*Bh]) ->
// shared fp16 accum HMMA (2x pipe rate if fp16-accum is double-rate), folded
// into fp32 at the epilogue.
// OUT_MODE: 0 = fp32, 1 = fp16 hi/lo pair, 2 = fp16 hi only.
template <int TERMS>
__device__ __forceinline__ void load_chunk(uint32_t sb, int buf,
                                           const half_t* Ah, const half_t* Al, int lda,
                                           const half_t* Bh, const half_t* Bl, int ldb,
                                           int tid, int kc) {
    uint32_t base = sb + buf * BUFB;
#pragma unroll
    for (int tile = 0; tile < 4; tile++) {
        if (TERMS == 2 && tile == 1) continue;   // no Al tile needed
        const half_t* gp = (tile == 0) ? Ah : (tile == 1) ? Al : (tile == 2) ? Bh : Bl;
        const int ld = (tile < 2) ? lda : ldb;
#pragma unroll
        for (int i = 0; i < 4; i++) {
            const int linear = tid + i * 128;   // 0..511
            const int row = linear >> 2, ch = linear & 3;
            CP_ASYNC_CG(base + tile * TILEB + row * ROWB + ch * 16,
                        gp + (ll)row * ld + kc * 32 + ch * 8);
        }
    }
    CP_COMMIT();
}

template <int OUT_MODE, int TERMS>
__global__ void __launch_bounds__(128, 2)
hgemm(const half_t* __restrict__ Ah, const half_t* __restrict__ Al, int lda, ll sA,
      const half_t* __restrict__ Bh, const half_t* __restrict__ Bl, int ldb, ll sB,
      float* __restrict__ Cf, half_t* __restrict__ Ch, half_t* __restrict__ Cl,
      int ldc, ll sC, int K, const float* __restrict__ bias) {
    extern __shared__ char smem[];
    const uint32_t sb = smem_u32(smem);
    const int tid = threadIdx.x, lane = tid & 31, wid = tid >> 5;
    const int warp_m = wid & 1, warp_n = wid >> 1;   // 2x2 warps, 64x64 each

    const ll z = blockIdx.z;
    const int bm = blockIdx.y * 128, bn = blockIdx.x * 128;
    Ah += z * sA + (ll)bm * lda;
    Al += z * sA + (ll)bm * lda;
    Bh += z * sB + (ll)bn * ldb;
    Bl += z * sB + (ll)bn * ldb;

    float acc[4][8][4];
    uint32_t acch[4][8][2];   // fp16x2 correction accumulators
#pragma unroll
    for (int i = 0; i < 4; i++)
#pragma unroll
        for (int j = 0; j < 8; j++) {
#pragma unroll
            for (int q = 0; q < 4; q++) acc[i][j][q] = 0.0f;
            acch[i][j][0] = 0u;
            acch[i][j][1] = 0u;
        }

    const uint32_t a_lane = (lane & 15) * ROWB + (lane >> 4) * 16;
    const uint32_t b_lane = (((lane >> 4) & 1) * 8 + (lane & 7)) * ROWB +
                            ((lane >> 3) & 1) * 16;

    const int nc = K >> 5;
    load_chunk<TERMS>(sb, 0, Ah, Al, lda, Bh, Bl, ldb, tid, 0);
    CP_WAIT0();
    __syncthreads();

    for (int c = 0; c < nc; c++) {
        const int buf = c & 1;
        if (c + 1 < nc)
            load_chunk<TERMS>(sb, buf ^ 1, Ah, Al, lda, Bh, Bl, ldb, tid, c + 1);

        const uint32_t Ab = sb + buf * BUFB;
        const uint32_t Bb = Ab + 2 * TILEB;
#pragma unroll
        for (int s = 0; s < 2; s++) {
            uint32_t ah[4][4], al[4][4];
#pragma unroll
            for (int mi = 0; mi < 4; mi++) {
                uint32_t base = Ab + (warp_m * 64 + mi * 16) * ROWB + s * 32 + a_lane;
                ldm_x4(ah[mi], base);
                if (TERMS == 3) ldm_x4(al[mi], base + TILEB);
            }
#pragma unroll
            for (int g = 0; g < 2; g++) {
                uint32_t bh[2][4], bl[2][4];
#pragma unroll
                for (int p = 0; p < 2; p++) {
                    uint32_t base = Bb + (warp_n * 64 + g * 32 + p * 16) * ROWB +
                                    s * 32 + b_lane;
                    ldm_x4(bh[p], base);
                    ldm_x4(bl[p], base + TILEB);
                }
                // main pass: Ah*Bh -> fp32 accum
#pragma unroll
                for (int mi = 0; mi < 4; mi++)
#pragma unroll
                    for (int nj = 0; nj < 4; nj++)
                        mma16816(acc[mi][g * 4 + nj], ah[mi], &bh[nj >> 1][(nj & 1) * 2]);
                // corr pass: Ah*Bl -> fp16 accum
#pragma unroll
                for (int mi = 0; mi < 4; mi++)
#pragma unroll
                    for (int nj = 0; nj < 4; nj++)
                        mma16816h(acch[mi][g * 4 + nj], ah[mi], &bl[nj >> 1][(nj & 1) * 2]);
                // corr pass: Al*Bh -> fp16 accum (shared)
                if (TERMS == 3) {
#pragma unroll
                    for (int mi = 0; mi < 4; mi++)
#pragma unroll
                        for (int nj = 0; nj < 4; nj++)
                            mma16816h(acch[mi][g * 4 + nj], al[mi],
                                      &bh[nj >> 1][(nj & 1) * 2]);
                }
            }
        }
        CP_WAIT0();
        __syncthreads();
    }

    const int row0 = bm + warp_m * 64 + (lane >> 2);
    const int colb = bn + warp_n * 64 + (lane & 3) * 2;
#pragma unroll
    for (int mi = 0; mi < 4; mi++) {
#pragma unroll
        for (int nj = 0; nj < 8; nj++) {
            const int r = row0 + mi * 16;
            const int c0 = colb + nj * 8;
            float b0v = bias ? bias[c0] : 0.0f;
            float b1v = bias ? bias[c0 + 1] : 0.0f;
            // fold fp16 corrections into fp32 results
            __half2 h2a = *(__half2*)&acch[mi][nj][0];   // row r:   c0, c0+1
            __half2 h2b = *(__half2*)&acch[mi][nj][1];   // row r+8: c0, c0+1
            float v0 = acc[mi][nj][0] + __low2float(h2a) + b0v;
            float v1 = acc[mi][nj][1] + __high2float(h2a) + b1v;
            float v2 = acc[mi][nj][2] + __low2float(h2b) + b0v;
            float v3 = acc[mi][nj][3] + __high2float(h2b) + b1v;
            if (OUT_MODE == 0) {
                *(float2*)(Cf + z * sC + (ll)r * ldc + c0) = make_float2(v0, v1);
                *(float2*)(Cf + z * sC + (ll)(r + 8) * ldc + c0) = make_float2(v2, v3);
            } else if (OUT_MODE == 1) {
                half_t h0, l0, h1, l1, h2, l2, h3, l3;
                split2h(v0, h0, l0); split2h(v1, h1, l1);
                split2h(v2, h2, l2); split2h(v3, h3, l3);
                ll o0 = z * sC + (ll)r * ldc + c0;
                ll o1 = z * sC + (ll)(r + 8) * ldc + c0;
                *(__half2*)(Ch + o0) = __halves2half2(h0, h1);
                *(__half2*)(Cl + o0) = __halves2half2(l0, l1);
                *(__half2*)(Ch + o1) = __halves2half2(h2, h3);
                *(__half2*)(Cl + o1) = __halves2half2(l2, l3);
            } else {
                ll o0 = z * sC + (ll)r * ldc + c0;
                ll o1 = z * sC + (ll)(r + 8) * ldc + c0;
                *(__half2*)(Ch + o0) =
                    __halves2half2(__float2half_rn(v0), __float2half_rn(v1));
                *(__half2*)(Ch + o1) =
                    __halves2half2(__float2half_rn(v2), __float2half_rn(v3));
            }
        }
    }
}

// ------------------------- launch -------------------------------------------
extern "C" void kernel_launch(void* const* d_in, const int* in_sizes, int n_in,
                              void* d_out, int out_size) {
    const float* x         = (const float*)d_in[0];
    const float* relations = (const float*)d_in[1];
    const float* re_w1     = (const float*)d_in[2];
    const float* re_b1     = (const float*)d_in[3];
    const float* re_w2     = (const float*)d_in[4];
    const float* re_b2     = (const float*)d_in[5];
    const float* attn_w    = (const float*)d_in[6];
    const float* out_w     = (const float*)d_in[7];
    const float* out_b     = (const float*)d_in[8];
    float* out = (float*)d_out;

    half_t *xH, *xL, *xTH, *xTL, *hidH, *hidL, *relH, *relL, *w2TH, *w2TL;
    half_t *awTH, *awTL, *owTH, *owTL, *scH, *scL, *atH, *ctxH;
    float* attnF;
    cudaGetSymbolAddress((void**)&xH, g_xH);     cudaGetSymbolAddress((void**)&xL, g_xL);
    cudaGetSymbolAddress((void**)&xTH, g_xTH);   cudaGetSymbolAddress((void**)&xTL, g_xTL);
    cudaGetSymbolAddress((void**)&hidH, g_hidH); cudaGetSymbolAddress((void**)&hidL, g_hidL);
    cudaGetSymbolAddress((void**)&relH, g_relH); cudaGetSymbolAddress((void**)&relL, g_relL);
    cudaGetSymbolAddress((void**)&w2TH, g_w2TH); cudaGetSymbolAddress((void**)&w2TL, g_w2TL);
    cudaGetSymbolAddress((void**)&awTH, g_awTH); cudaGetSymbolAddress((void**)&awTL, g_awTL);
    cudaGetSymbolAddress((void**)&owTH, g_owTH); cudaGetSymbolAddress((void**)&owTL, g_owTL);
    cudaGetSymbolAddress((void**)&scH, g_scH);   cudaGetSymbolAddress((void**)&scL, g_scL);
    cudaGetSymbolAddress((void**)&atH, g_atH);
    cudaGetSymbolAddress((void**)&ctxH, g_ctxH);
    cudaGetSymbolAddress((void**)&attnF, g_attnF);

    cudaFuncSetAttribute(hgemm<0, 3>, cudaFuncAttributeMaxDynamicSharedMemorySize, SMEM_TOTAL);
    cudaFuncSetAttribute(hgemm<1, 3>, cudaFuncAttributeMaxDynamicSharedMemorySize, SMEM_TOTAL);
    cudaFuncSetAttribute(hgemm<2, 2>, cudaFuncAttributeMaxDynamicSharedMemorySize, SMEM_TOTAL);
    cudaFuncSetAttribute(hgemm<0, 2>, cudaFuncAttributeMaxDynamicSharedMemorySize, SMEM_TOTAL);

    // Launch order keeps the 4th launch (ncu capture slot) = stage-3 hgemm.
    split_x_kernel<<<S * D / 256, 256>>>(x);                                    // 1
    transpose_split<<<dim3(D / 32, D / 32, H), dim3(32, 8)>>>(attn_w, (ll)D * D, D, D,
                                                              awTH, awTL, (ll)D * D);  // 2
    relenc1_kernel<<<S * D / 256, 256>>>(relations, re_w1, re_b1);              // 3

    // 3) scores_h = x @ attn_w[h]^T -> [H,S,D] raw layout        (launch 4: profiled)
    hgemm<1, 3><<<dim3(D / 128, S / 128, H), 128, SMEM_TOTAL>>>(
        xH, xL, D, 0, awTH, awTL, D, (ll)D * D,
        nullptr, scH, scL, D, (ll)S * D, D, nullptr);

    transpose_split<<<dim3(D / 32, D / 32, 1), dim3(32, 8)>>>(re_w2, 0, D, D, w2TH, w2TL, 0);

    // 2) rel = hidden @ re_w2 + b2
    hgemm<1, 3><<<dim3(D / 128, S / 128, 1), 128, SMEM_TOTAL>>>(
        hidH, hidL, D, 0, w2TH, w2TL, D, 0, nullptr, relH, relL, D, 0, D, re_b2);

    // 4) rel_scores via raw reshape read
    hgemm<0, 3><<<dim3(S / 128, S / 128, H), 128, SMEM_TOTAL>>>(
        relH, relL, D, 0, scH, scL, HD, (ll)D,
        attnF, nullptr, nullptr, S, (ll)S * S, D, nullptr);

    // 5) softmax -> fp16 hi only
    softmax_kernel<<<H * S, 256>>>();

    transpose_split<<<dim3(D / 32, S / 32, 1), dim3(32, 8)>>>(x, 0, S, D, xTH, xTL, 0);

    // 6) ctx = attn @ x -> fp16 hi only   (2-term)
    hgemm<2, 2><<<dim3(D / 128, S / 128, H), 128, SMEM_TOTAL>>>(
        atH, atH, S, (ll)S * S, xTH, xTL, S, 0,
        nullptr, ctxH, nullptr, HD, (ll)D, S, nullptr);

    transpose_split<<<dim3(D / 32, HD / 32, 1), dim3(32, 8)>>>(out_w, 0, HD, D, owTH, owTL, 0);

    // 7) out = ctx @ out_w + out_b -> fp32   (2-term)
    hgemm<0, 2><<<dim3(D / 128, S / 128, 1), 128, SMEM_TOTAL>>>(
        ctxH, ctxH, HD, 0, owTH, owTL, HD, 0,
        out, nullptr, nullptr, D, 0, HD, out_b);
}

// round 17
// speedup vs baseline: 1.1848x; 1.1848x over previous
#include <cuda_runtime.h>
#include <cuda_fp16.h>
#include <math.h>
#include <stdint.h>

#define S 2048
#define D 1024
#define H 8
#define HD 8192

typedef __half half_t;
typedef long long ll;

// ------------------------- scratch (device globals) -------------------------
__device__ __align__(256) half_t g_xH[S * D], g_xL[S * D];
__device__ __align__(256) half_t g_xTH[D * S], g_xTL[D * S];
__device__ __align__(256) half_t g_hidH[S * D], g_hidL[S * D];
__device__ __align__(256) half_t g_relH[S * D], g_relL[S * D];
__device__ __align__(256) half_t g_w2TH[D * D], g_w2TL[D * D];
__device__ __align__(256) half_t g_awTH[H * D * D], g_awTL[H * D * D];
__device__ __align__(256) half_t g_owTH[D * HD], g_owTL[D * HD];
__device__ __align__(256) half_t g_scH[S * HD], g_scL[S * HD];   // [H,S,D] raw
__device__ __align__(256) float  g_attnF[(size_t)H * S * S];
__device__ __align__(256) half_t g_atH[(size_t)H * S * S];       // hi only
__device__ __align__(256) half_t g_ctxH[S * HD];                 // hi only

// ------------------------- helpers ------------------------------------------
__device__ __forceinline__ uint32_t smem_u32(const void* p) {
    uint32_t a;
    asm("{ .reg .u64 t; cvta.to.shared.u64 t, %1; cvt.u32.u64 %0, t; }"
        : "=r"(a) : "l"(p));
    return a;
}
__device__ __forceinline__ void split2h(float v, half_t& h, half_t& l) {
    h = __float2half_rn(v);
    l = __float2half_rn(v - __half2float(h));
}
__device__ __forceinline__ void ldm_x4(uint32_t* r, uint32_t addr) {
    asm volatile("ldmatrix.sync.aligned.m8n8.x4.shared.b16 {%0,%1,%2,%3}, [%4];"
                 : "=r"(r[0]), "=r"(r[1]), "=r"(r[2]), "=r"(r[3]) : "r"(addr));
}
__device__ __forceinline__ void mma16816(float* c, const uint32_t* a, const uint32_t* b) {
    asm volatile(
        "mma.sync.aligned.m16n8k16.row.col.f32.f16.f16.f32 "
        "{%0,%1,%2,%3}, {%4,%5,%6,%7}, {%8,%9}, {%0,%1,%2,%3};"
        : "+f"(c[0]), "+f"(c[1]), "+f"(c[2]), "+f"(c[3])
        : "r"(a[0]), "r"(a[1]), "r"(a[2]), "r"(a[3]), "r"(b[0]), "r"(b[1]));
}
#define CP_ASYNC_CG(sa, g) \
    asm volatile("cp.async.cg.shared.global [%0], [%1], 16;" :: "r"(sa), "l"(g) : "memory")
#define CP_COMMIT()  asm volatile("cp.async.commit_group;" ::: "memory")
#define CP_WAIT0()   asm volatile("cp.async.wait_group 0;" ::: "memory")

// SMEM tile geometry: 128 rows x 32 halves, padded row = 80 bytes
#define ROWB 80
#define TILEB (128 * ROWB)       // 10240
#define BUFB (4 * TILEB)         // 40960 per stage
#define SMEM_TOTAL (2 * BUFB)    // 81920

// ------------------------- conversion kernels -------------------------------
__global__ void split_x_kernel(const float* __restrict__ x) {
    int i = blockIdx.x * 256 + threadIdx.x;
    split2h(x[i], g_xH[i], g_xL[i]);
}

__global__ void relenc1_kernel(const float* __restrict__ relations,
                               const float* __restrict__ w1,
                               const float* __restrict__ b1) {
    int idx = blockIdx.x * 256 + threadIdx.x;
    int s = idx >> 10, d = idx & 1023;
    float v = b1[d];
    v = fmaf(relations[s * 4 + 0], w1[0 * D + d], v);
    v = fmaf(relations[s * 4 + 1], w1[1 * D + d], v);
    v = fmaf(relations[s * 4 + 2], w1[2 * D + d], v);
    v = fmaf(relations[s * 4 + 3], w1[3 * D + d], v);
    v = fmaxf(v, 0.0f);
    split2h(v, g_hidH[idx], g_hidL[idx]);
}

__global__ void transpose_split(const float* __restrict__ in, ll sIn,
                                int R, int C,
                                half_t* __restrict__ oH, half_t* __restrict__ oL,
                                ll sOut) {
    __shared__ float t[32][33];
    in += (ll)blockIdx.z * sIn;
    oH += (ll)blockIdx.z * sOut;
    oL += (ll)blockIdx.z * sOut;
    int r0 = blockIdx.y * 32, c0 = blockIdx.x * 32;
    int tx = threadIdx.x, ty = threadIdx.y;  // 32 x 8
#pragma unroll
    for (int i = 0; i < 4; i++)
        t[ty + i * 8][tx] = in[(ll)(r0 + ty + i * 8) * C + c0 + tx];
    __syncthreads();
#pragma unroll
    for (int i = 0; i < 4; i++) {
        float v = t[tx][ty + i * 8];
        ll o = (ll)(c0 + ty + i * 8) * R + r0 + tx;
        half_t h, l;
        split2h(v, h, l);
        oH[o] = h;
        oL[o] = l;
    }
}

// ------------------------- softmax ------------------------------------------
__global__ void softmax_kernel() {
    const ll row = blockIdx.x;  // H*S rows
    const float4* p = (const float4*)(g_attnF + row * (ll)S);
    const int tid = threadIdx.x;  // 256
    float4 a = p[tid];
    float4 b = p[tid + 256];
    __shared__ float red[8];

    float m = fmaxf(fmaxf(fmaxf(a.x, a.y), fmaxf(a.z, a.w)),
                    fmaxf(fmaxf(b.x, b.y), fmaxf(b.z, b.w)));
#pragma unroll
    for (int o = 16; o > 0; o >>= 1) m = fmaxf(m, __shfl_xor_sync(~0u, m, o));
    if ((tid & 31) == 0) red[tid >> 5] = m;
    __syncthreads();
    if (tid < 32) {
        float t = (tid < 8) ? red[tid] : -INFINITY;
#pragma unroll
        for (int o = 4; o > 0; o >>= 1) t = fmaxf(t, __shfl_xor_sync(~0u, t, o));
        if (tid == 0) red[0] = t;
    }
    __syncthreads();
    m = red[0];
    __syncthreads();

    a.x = expf(a.x - m); a.y = expf(a.y - m); a.z = expf(a.z - m); a.w = expf(a.w - m);
    b.x = expf(b.x - m); b.y = expf(b.y - m); b.z = expf(b.z - m); b.w = expf(b.w - m);
    float s = a.x + a.y + a.z + a.w + b.x + b.y + b.z + b.w;
#pragma unroll
    for (int o = 16; o > 0; o >>= 1) s += __shfl_xor_sync(~0u, s, o);
    if ((tid & 31) == 0) red[tid >> 5] = s;
    __syncthreads();
    if (tid < 32) {
        float t = (tid < 8) ? red[tid] : 0.0f;
#pragma unroll
        for (int o = 4; o > 0; o >>= 1) t += __shfl_xor_sync(~0u, t, o);
        if (tid == 0) red[0] = t;
    }
    __syncthreads();
    float inv = 1.0f / red[0];

    half_t h[8];
    h[0] = __float2half_rn(a.x * inv); h[1] = __float2half_rn(a.y * inv);
    h[2] = __float2half_rn(a.z * inv); h[3] = __float2half_rn(a.w * inv);
    h[4] = __float2half_rn(b.x * inv); h[5] = __float2half_rn(b.y * inv);
    h[6] = __float2half_rn(b.z * inv); h[7] = __float2half_rn(b.w * inv);
    ll b0 = row * (ll)S + tid * 4;
    *(uint2*)(g_atH + b0) = *(uint2*)&h[0];
    *(uint2*)(g_atH + b0 + 1024) = *(uint2*)&h[4];
}

// ------------------------- split-fp16 NT HGEMM (mma.sync) --------------------
// 128-thread CTA, 4 warps of 64x64; CTA tile 128x128, BK=32, 2-stage ring.
// TERMS==3: Ah*Bh + Ah*Bl + Al*Bh.  TERMS==2: Ah*Bh + Ah*Bl.  TERMS==1: Ah*Bh.
// OUT_MODE: 0 = fp32, 1 = fp16 hi/lo pair, 2 = fp16 hi only.
template <int TERMS>
__device__ __forceinline__ void load_chunk(uint32_t sb, int buf,
                                           const half_t* Ah, const half_t* Al, int lda,
                                           const half_t* Bh, const half_t* Bl, int ldb,
                                           int tid, int kc) {
    uint32_t base = sb + buf * BUFB;
#pragma unroll
    for (int tile = 0; tile < 4; tile++) {
        if (TERMS <= 2 && tile == 1) continue;   // no Al tile
        if (TERMS == 1 && tile == 3) continue;   // no Bl tile
        const half_t* gp = (tile == 0) ? Ah : (tile == 1) ? Al : (tile == 2) ? Bh : Bl;
        const int ld = (tile < 2) ? lda : ldb;
#pragma unroll
        for (int i = 0; i < 4; i++) {
            const int linear = tid + i * 128;   // 0..511
            const int row = linear >> 2, ch = linear & 3;
            CP_ASYNC_CG(base + tile * TILEB + row * ROWB + ch * 16,
                        gp + (ll)row * ld + kc * 32 + ch * 8);
        }
    }
    CP_COMMIT();
}

template <int OUT_MODE, int TERMS>
__global__ void __launch_bounds__(128, 2)
hgemm(const half_t* __restrict__ Ah, const half_t* __restrict__ Al, int lda, ll sA,
      const half_t* __restrict__ Bh, const half_t* __restrict__ Bl, int ldb, ll sB,
      float* __restrict__ Cf, half_t* __restrict__ Ch, half_t* __restrict__ Cl,
      int ldc, ll sC, int K, const float* __restrict__ bias) {
    extern __shared__ char smem[];
    const uint32_t sb = smem_u32(smem);
    const int tid = threadIdx.x, lane = tid & 31, wid = tid >> 5;
    const int warp_m = wid & 1, warp_n = wid >> 1;   // 2x2 warps, 64x64 each

    const ll z = blockIdx.z;
    const int bm = blockIdx.y * 128, bn = blockIdx.x * 128;
    Ah += z * sA + (ll)bm * lda;
    Al += z * sA + (ll)bm * lda;
    Bh += z * sB + (ll)bn * ldb;
    Bl += z * sB + (ll)bn * ldb;

    float acc[4][8][4];
#pragma unroll
    for (int i = 0; i < 4; i++)
#pragma unroll
        for (int j = 0; j < 8; j++)
#pragma unroll
            for (int q = 0; q < 4; q++) acc[i][j][q] = 0.0f;

    const uint32_t a_lane = (lane & 15) * ROWB + (lane >> 4) * 16;
    const uint32_t b_lane = (((lane >> 4) & 1) * 8 + (lane & 7)) * ROWB +
                            ((lane >> 3) & 1) * 16;

    const int nc = K >> 5;
    load_chunk<TERMS>(sb, 0, Ah, Al, lda, Bh, Bl, ldb, tid, 0);
    CP_WAIT0();
    __syncthreads();

    for (int c = 0; c < nc; c++) {
        const int buf = c & 1;
        if (c + 1 < nc)
            load_chunk<TERMS>(sb, buf ^ 1, Ah, Al, lda, Bh, Bl, ldb, tid, c + 1);

        const uint32_t Ab = sb + buf * BUFB;
        const uint32_t Bb = Ab + 2 * TILEB;
#pragma unroll
        for (int s = 0; s < 2; s++) {
            uint32_t ah[4][4], al[4][4];
#pragma unroll
            for (int mi = 0; mi < 4; mi++) {
                uint32_t base = Ab + (warp_m * 64 + mi * 16) * ROWB + s * 32 + a_lane;
                ldm_x4(ah[mi], base);
                if (TERMS == 3) ldm_x4(al[mi], base + TILEB);
            }
#pragma unroll
            for (int g = 0; g < 2; g++) {
                uint32_t bh[2][4], bl[2][4];
#pragma unroll
                for (int p = 0; p < 2; p++) {
                    uint32_t base = Bb + (warp_n * 64 + g * 32 + p * 16) * ROWB +
                                    s * 32 + b_lane;
                    ldm_x4(bh[p], base);
                    if (TERMS >= 2) ldm_x4(bl[p], base + TILEB);
                }
                // main pass: Ah*Bh  (16 independent)
#pragma unroll
                for (int mi = 0; mi < 4; mi++)
#pragma unroll
                    for (int nj = 0; nj < 4; nj++)
                        mma16816(acc[mi][g * 4 + nj], ah[mi], &bh[nj >> 1][(nj & 1) * 2]);
                // corr pass: Ah*Bl
                if (TERMS >= 2) {
#pragma unroll
                    for (int mi = 0; mi < 4; mi++)
#pragma unroll
                        for (int nj = 0; nj < 4; nj++)
                            mma16816(acc[mi][g * 4 + nj], ah[mi],
                                     &bl[nj >> 1][(nj & 1) * 2]);
                }
                // corr pass: Al*Bh
                if (TERMS == 3) {
#pragma unroll
                    for (int mi = 0; mi < 4; mi++)
#pragma unroll
                        for (int nj = 0; nj < 4; nj++)
                            mma16816(acc[mi][g * 4 + nj], al[mi],
                                     &bh[nj >> 1][(nj & 1) * 2]);
                }
            }
        }
        CP_WAIT0();
        __syncthreads();
    }

    const int row0 = bm + warp_m * 64 + (lane >> 2);
    const int colb = bn + warp_n * 64 + (lane & 3) * 2;
#pragma unroll
    for (int mi = 0; mi < 4; mi++) {
#pragma unroll
        for (int nj = 0; nj < 8; nj++) {
            const int r = row0 + mi * 16;
            const int c0 = colb + nj * 8;
            float b0v = bias ? bias[c0] : 0.0f;
            float b1v = bias ? bias[c0 + 1] : 0.0f;
            float v0 = acc[mi][nj][0] + b0v, v1 = acc[mi][nj][1] + b1v;
            float v2 = acc[mi][nj][2] + b0v, v3 = acc[mi][nj][3] + b1v;
            if (OUT_MODE == 0) {
                *(float2*)(Cf + z * sC + (ll)r * ldc + c0) = make_float2(v0, v1);
                *(float2*)(Cf + z * sC + (ll)(r + 8) * ldc + c0) = make_float2(v2, v3);
            } else if (OUT_MODE == 1) {
                half_t h0, l0, h1, l1, h2, l2, h3, l3;
                split2h(v0, h0, l0); split2h(v1, h1, l1);
                split2h(v2, h2, l2); split2h(v3, h3, l3);
                ll o0 = z * sC + (ll)r * ldc + c0;
                ll o1 = z * sC + (ll)(r + 8) * ldc + c0;
                *(__half2*)(Ch + o0) = __halves2half2(h0, h1);
                *(__half2*)(Cl + o0) = __halves2half2(l0, l1);
                *(__half2*)(Ch + o1) = __halves2half2(h2, h3);
                *(__half2*)(Cl + o1) = __halves2half2(l2, l3);
            } else {
                ll o0 = z * sC + (ll)r * ldc + c0;
                ll o1 = z * sC + (ll)(r + 8) * ldc + c0;
                *(__half2*)(Ch + o0) =
                    __halves2half2(__float2half_rn(v0), __float2half_rn(v1));
                *(__half2*)(Ch + o1) =
                    __halves2half2(__float2half_rn(v2), __float2half_rn(v3));
            }
        }
    }
}

// ------------------------- launch -------------------------------------------
extern "C" void kernel_launch(void* const* d_in, const int* in_sizes, int n_in,
                              void* d_out, int out_size) {
    const float* x         = (const float*)d_in[0];
    const float* relations = (const float*)d_in[1];
    const float* re_w1     = (const float*)d_in[2];
    const float* re_b1     = (const float*)d_in[3];
    const float* re_w2     = (const float*)d_in[4];
    const float* re_b2     = (const float*)d_in[5];
    const float* attn_w    = (const float*)d_in[6];
    const float* out_w     = (const float*)d_in[7];
    const float* out_b     = (const float*)d_in[8];
    float* out = (float*)d_out;

    half_t *xH, *xL, *xTH, *xTL, *hidH, *hidL, *relH, *relL, *w2TH, *w2TL;
    half_t *awTH, *awTL, *owTH, *owTL, *scH, *scL, *atH, *ctxH;
    float* attnF;
    cudaGetSymbolAddress((void**)&xH, g_xH);     cudaGetSymbolAddress((void**)&xL, g_xL);
    cudaGetSymbolAddress((void**)&xTH, g_xTH);   cudaGetSymbolAddress((void**)&xTL, g_xTL);
    cudaGetSymbolAddress((void**)&hidH, g_hidH); cudaGetSymbolAddress((void**)&hidL, g_hidL);
    cudaGetSymbolAddress((void**)&relH, g_relH); cudaGetSymbolAddress((void**)&relL, g_relL);
    cudaGetSymbolAddress((void**)&w2TH, g_w2TH); cudaGetSymbolAddress((void**)&w2TL, g_w2TL);
    cudaGetSymbolAddress((void**)&awTH, g_awTH); cudaGetSymbolAddress((void**)&awTL, g_awTL);
    cudaGetSymbolAddress((void**)&owTH, g_owTH); cudaGetSymbolAddress((void**)&owTL, g_owTL);
    cudaGetSymbolAddress((void**)&scH, g_scH);   cudaGetSymbolAddress((void**)&scL, g_scL);
    cudaGetSymbolAddress((void**)&atH, g_atH);
    cudaGetSymbolAddress((void**)&ctxH, g_ctxH);
    cudaGetSymbolAddress((void**)&attnF, g_attnF);

    cudaFuncSetAttribute(hgemm<0, 3>, cudaFuncAttributeMaxDynamicSharedMemorySize, SMEM_TOTAL);
    cudaFuncSetAttribute(hgemm<1, 3>, cudaFuncAttributeMaxDynamicSharedMemorySize, SMEM_TOTAL);
    cudaFuncSetAttribute(hgemm<2, 1>, cudaFuncAttributeMaxDynamicSharedMemorySize, SMEM_TOTAL);
    cudaFuncSetAttribute(hgemm<0, 1>, cudaFuncAttributeMaxDynamicSharedMemorySize, SMEM_TOTAL);

    // Launch order keeps the 4th launch (ncu capture slot) = stage-3 hgemm.
    split_x_kernel<<<S * D / 256, 256>>>(x);                                    // 1
    transpose_split<<<dim3(D / 32, D / 32, H), dim3(32, 8)>>>(attn_w, (ll)D * D, D, D,
                                                              awTH, awTL, (ll)D * D);  // 2
    relenc1_kernel<<<S * D / 256, 256>>>(relations, re_w1, re_b1);              // 3

    // 3) scores_h = x @ attn_w[h]^T -> [H,S,D] raw layout        (launch 4: profiled)
    hgemm<1, 3><<<dim3(D / 128, S / 128, H), 128, SMEM_TOTAL>>>(
        xH, xL, D, 0, awTH, awTL, D, (ll)D * D,
        nullptr, scH, scL, D, (ll)S * D, D, nullptr);

    transpose_split<<<dim3(D / 32, D / 32, 1), dim3(32, 8)>>>(re_w2, 0, D, D, w2TH, w2TL, 0);

    // 2) rel = hidden @ re_w2 + b2   (3-term: score chain precision)
    hgemm<1, 3><<<dim3(D / 128, S / 128, 1), 128, SMEM_TOTAL>>>(
        hidH, hidL, D, 0, w2TH, w2TL, D, 0, nullptr, relH, relL, D, 0, D, re_b2);

    // 4) rel_scores via raw reshape read   (3-term)
    hgemm<0, 3><<<dim3(S / 128, S / 128, H), 128, SMEM_TOTAL>>>(
        relH, relL, D, 0, scH, scL, HD, (ll)D,
        attnF, nullptr, nullptr, S, (ll)S * S, D, nullptr);

    // 5) softmax -> fp16 hi only
    softmax_kernel<<<H * S, 256>>>();

    transpose_split<<<dim3(D / 32, S / 32, 1), dim3(32, 8)>>>(x, 0, S, D, xTH, xTL, 0);

    // 6) ctx = attn @ x -> fp16 hi only   (1-term: attnH * xH, post-softmax linear)
    hgemm<2, 1><<<dim3(D / 128, S / 128, H), 128, SMEM_TOTAL>>>(
        atH, atH, S, (ll)S * S, xTH, xTH, S, 0,
        nullptr, ctxH, nullptr, HD, (ll)D, S, nullptr);

    transpose_split<<<dim3(D / 32, HD / 32, 1), dim3(32, 8)>>>(out_w, 0, HD, D, owTH, owTL, 0);

    // 7) out = ctx @ out_w + out_b -> fp32   (1-term: ctxH * owH)
    hgemm<0, 1><<<dim3(D / 128, S / 128, 1), 128, SMEM_TOTAL>>>(
        ctxH, ctxH, HD, 0, owTH, owTH, HD, 0,
        out, nullptr, nullptr, D, 0, HD, out_b);
}